// round 13
// baseline (speedup 1.0000x reference)
#include <cuda_runtime.h>
#include <cuda_fp16.h>
#include <cstdint>

#define DINL __device__ __forceinline__

// ---------------------------------------------------------------------------
// Problem constants
// ---------------------------------------------------------------------------
namespace {
constexpr int M_TOT = 32768;          // B*T
constexpr int K1 = 768,  N1 = 2048;   // GEMM1: x @ Wg/Wu (fused SwiGLU)
constexpr int K2 = 2048, N2 = 768;    // GEMM2: h @ Wd
constexpr int BK = 128;               // K per chunk (doubled sync-free window)
constexpr int NC1 = K1 / BK;          // 6 chunks
constexpr int NC2 = K2 / BK;          // 16 chunks

constexpr int LDKB = 136;             // smem halves per row (128 + 8 pad)
constexpr int ROWB = LDKB * 2;        // 272 bytes per row
constexpr int TILEA = 128 * ROWB;     // 34816 B per 128-row tile
constexpr int STG1 = 3 * TILEA;       // gemm1 stage: A + Bg + Bu = 104448
constexpr int STG2 = 2 * TILEA;       // gemm2 stage: A + B      = 69632
constexpr int NSTG1 = 2;
constexpr int NSTG2 = 3;
constexpr int SMEM1 = NSTG1 * STG1;   // 208896
constexpr int SMEM2 = NSTG2 * STG2;   // 208896
constexpr int FSTR = 16 * ROWB;       // 16-row fragment stride = 4352
}

// ---------------------------------------------------------------------------
// Device scratch (static __device__ globals: allocation-free)
// ---------------------------------------------------------------------------
__device__ __half g_x [(size_t)M_TOT * K1];   // x fp16, row-major [32768,768]
__device__ __half g_h [(size_t)M_TOT * N1];   // hidden fp16 [32768,2048]
__device__ __half g_wg[(size_t)N1 * K1];      // gate signs, [n][k]
__device__ __half g_wu[(size_t)N1 * K1];      // up signs,   [n][k]
__device__ __half g_wd[(size_t)N2 * K2];      // down signs, [n][k]
__device__ float  g_scales[3];                // absmean scales: gate, up, down

// Octonion Cayley table: e_i * e_j = STAB[i][j] * e_{KTAB[i][j]}
__constant__ signed char KTAB[8][8] = {
    {0,1,2,3,4,5,6,7},
    {1,0,3,2,5,4,7,6},
    {2,3,0,1,6,7,4,5},
    {3,2,1,0,7,6,5,4},
    {4,5,6,7,0,1,2,3},
    {5,4,7,6,1,0,3,2},
    {6,7,4,5,2,3,0,1},
    {7,6,5,4,3,2,1,0},
};
__constant__ signed char STAB[8][8] = {
    { 1, 1, 1, 1, 1, 1, 1, 1},
    { 1,-1, 1,-1, 1,-1,-1, 1},
    { 1,-1,-1, 1, 1, 1,-1,-1},
    { 1, 1,-1,-1, 1,-1, 1,-1},
    { 1,-1,-1,-1,-1, 1, 1, 1},
    { 1, 1,-1, 1,-1,-1,-1, 1},
    { 1, 1, 1,-1,-1, 1,-1,-1},
    { 1,-1, 1, 1,-1,-1, 1,-1},
};

// ---------------------------------------------------------------------------
// PTX helpers (sm_80-portable only)
// ---------------------------------------------------------------------------
DINL uint32_t smem_u32(const void* p) {
    uint32_t a;
    asm("{ .reg .u64 t; cvta.to.shared.u64 t, %1; cvt.u32.u64 %0, t; }"
        : "=r"(a) : "l"(p));
    return a;
}
DINL void cp_async16(uint32_t dst, const void* src) {
    asm volatile("cp.async.cg.shared.global [%0], [%1], 16;"
                 :: "r"(dst), "l"(src) : "memory");
}
DINL void cp_commit() { asm volatile("cp.async.commit_group;" ::: "memory"); }
template <int N> DINL void cp_wait() {
    asm volatile("cp.async.wait_group %0;" :: "n"(N) : "memory");
}
DINL void ldm_x4(uint32_t* r, uint32_t addr) {
    asm volatile("ldmatrix.sync.aligned.m8n8.x4.shared.b16 {%0,%1,%2,%3}, [%4];"
                 : "=r"(r[0]), "=r"(r[1]), "=r"(r[2]), "=r"(r[3]) : "r"(addr));
}
DINL void mma16816(float* d, const uint32_t* a, uint32_t b0, uint32_t b1) {
    asm volatile(
        "mma.sync.aligned.m16n8k16.row.col.f32.f16.f16.f32 "
        "{%0,%1,%2,%3}, {%4,%5,%6,%7}, {%8,%9}, {%0,%1,%2,%3};"
        : "+f"(d[0]), "+f"(d[1]), "+f"(d[2]), "+f"(d[3])
        : "r"(a[0]), "r"(a[1]), "r"(a[2]), "r"(a[3]), "r"(b0), "r"(b1));
}

// ---------------------------------------------------------------------------
// Prep kernels
// ---------------------------------------------------------------------------
__global__ void scales_kernel(const float* wg, const float* wu, const float* wd) {
    const float* w = (blockIdx.x == 0) ? wg : (blockIdx.x == 1) ? wu : wd;
    __shared__ double red[256];
    const int tid = threadIdx.x;
    double s = 0.0;
    for (int i = tid; i < 196608; i += 256) s += fabsf(w[i]);
    red[tid] = s;
    __syncthreads();
    for (int off = 128; off > 0; off >>= 1) {
        if (tid < off) red[tid] += red[tid + off];
        __syncthreads();
    }
    if (tid == 0)
        g_scales[blockIdx.x] = (float)(red[0] / 196608.0) + 1e-8f;
}

// Build all three sign matrices. blockIdx.y: 0=gate, 1=up, 2=down.
__global__ void build_w_kernel(const float* wgate, const float* wup,
                               const float* wdown) {
    const int gid = blockIdx.x * 256 + threadIdx.x;
    const int which = blockIdx.y;
    const float scale = g_scales[which];
    float v;
    __half* o;
    if (which < 2) {
        const float* w = which ? wup : wgate;
        const int n = gid / K1, k = gid % K1;
        const int kk = n >> 8, c = n & 255;
        const int i = k / 96, r = k % 96;
        int j = 0;
        while (KTAB[i][j] != kk) ++j;
        v = (float)STAB[i][j] * w[(j * 96 + r) * 256 + c];
        o = which ? g_wu : g_wg;
    } else {
        const int n = gid / K2, k = gid % K2;
        const int kk = n / 96, c = n % 96;
        const int i = k >> 8, r = k & 255;
        int j = 0;
        while (KTAB[i][j] != kk) ++j;
        v = (float)STAB[i][j] * wdown[(j * 256 + r) * 96 + c];
        o = g_wd;
    }
    float q = fminf(fmaxf(rintf(v / scale), -1.f), 1.f);  // exact {-1,0,1}
    o[gid] = __float2half_rn(q);
}

// x fp32 -> fp16
__global__ void convert_x_kernel(const float4* __restrict__ x) {
    const int total4 = (M_TOT * K1) / 4;
    for (int i = blockIdx.x * 256 + threadIdx.x; i < total4; i += 6144 * 256) {
        float4 v = x[i];
        __half2 a = __floats2half2_rn(v.x, v.y);
        __half2 b = __floats2half2_rn(v.z, v.w);
        uint2 pk;
        pk.x = *reinterpret_cast<uint32_t*>(&a);
        pk.y = *reinterpret_cast<uint32_t*>(&b);
        reinterpret_cast<uint2*>(g_x)[i] = pk;
    }
}

// ---------------------------------------------------------------------------
// GEMM1: h = silu(x@Wg * sg) * (x@Wu * su)  -> g_h fp16
// CTA 128x128, BK=128 (8 ks-steps per barrier), 512 threads,
// 16 warps as 2(M) x 8(N), warp tile 64x16 (x2 gate/up), 2-stage pipeline.
// One barrier per K=128 — 2x wider sync-free window than before.
// ---------------------------------------------------------------------------
__global__ void __launch_bounds__(512, 1) gemm1_kernel() {
    extern __shared__ __align__(128) char sm[];
    const int tid = threadIdx.x, wid = tid >> 5, lid = tid & 31;
    const int m0 = blockIdx.y * 128, n0 = blockIdx.x * 128;
    const int wm0 = (wid & 1) * 64, wn0 = (wid >> 1) * 16;
    const uint32_t sb = smem_u32(sm);

    // 128 rows x 16 segs of 16B per tile; 512 threads -> 4 iters per tile.
    auto load_chunk = [&](int c, int s) {
        const uint32_t st = sb + s * STG1;
        const int kb = c * BK;
#pragma unroll
        for (int i = 0; i < 4; ++i) {
            int idx = tid + i * 512, row = idx >> 4, seg = idx & 15;
            uint32_t off = (uint32_t)(row * ROWB + seg * 16);
            cp_async16(st + off, g_x + (size_t)(m0 + row) * K1 + kb + seg * 8);
            cp_async16(st + TILEA + off,
                       g_wg + (size_t)(n0 + row) * K1 + kb + seg * 8);
            cp_async16(st + 2 * TILEA + off,
                       g_wu + (size_t)(n0 + row) * K1 + kb + seg * 8);
        }
        cp_commit();
    };

    load_chunk(0, 0);

    float accg[4][2][4], accu[4][2][4];
#pragma unroll
    for (int a = 0; a < 4; ++a)
#pragma unroll
        for (int b = 0; b < 2; ++b)
#pragma unroll
            for (int c = 0; c < 4; ++c) { accg[a][b][c] = 0.f; accu[a][b][c] = 0.f; }

    const int lr = lid & 15, hc = lid >> 4;
    const uint32_t a_off = (uint32_t)((wm0 + lr) * ROWB + hc * 16);
    const uint32_t b_off = (uint32_t)((wn0 + lr) * ROWB + hc * 16);

#pragma unroll 1
    for (int mc = 0; mc < NC1; ++mc) {
        cp_wait<0>();          // chunk mc fully resident
        __syncthreads();       // protects stage (mc+1)%2 from late readers
        if (mc + 1 < NC1) load_chunk(mc + 1, (mc + 1) & 1);

        const uint32_t st  = sb + (mc & 1) * STG1;
        const uint32_t aB  = st + a_off;
        const uint32_t bgB = st + TILEA + b_off;
        const uint32_t buB = bgB + TILEA;

#pragma unroll
        for (int ks = 0; ks < 8; ++ks) {
            const uint32_t ko = ks * 32;
            uint32_t a[4][4], bg[4], bu[4];
#pragma unroll
            for (int mf = 0; mf < 4; ++mf)
                ldm_x4(a[mf], aB + mf * FSTR + ko);
            ldm_x4(bg, bgB + ko);
            ldm_x4(bu, buB + ko);
#pragma unroll
            for (int mf = 0; mf < 4; ++mf)
#pragma unroll
                for (int nf = 0; nf < 2; ++nf) {
                    mma16816(accg[mf][nf], a[mf], bg[nf], bg[nf + 2]);
                    mma16816(accu[mf][nf], a[mf], bu[nf], bu[nf + 2]);
                }
        }
    }

    // ---- fused SwiGLU epilogue -> g_h (fp16)
    const float sg = g_scales[0], su = g_scales[1];
    const int g = lid >> 2, t = lid & 3;
    __half2* hout = reinterpret_cast<__half2*>(g_h);
#pragma unroll
    for (int mf = 0; mf < 4; ++mf)
#pragma unroll
        for (int nf = 0; nf < 2; ++nf) {
            const int row0 = m0 + wm0 + mf * 16 + g;
            const int col  = n0 + wn0 + nf * 8 + 2 * t;
            const float* dg = accg[mf][nf];
            const float* du = accu[mf][nf];
#pragma unroll
            for (int h = 0; h < 2; ++h) {
                float g0 = dg[2 * h] * sg,     g1 = dg[2 * h + 1] * sg;
                float u0 = du[2 * h] * su,     u1 = du[2 * h + 1] * su;
                float h0 = g0 / (1.f + __expf(-g0)) * u0;
                float h1 = g1 / (1.f + __expf(-g1)) * u1;
                hout[(size_t)(row0 + 8 * h) * (N1 / 2) + (col >> 1)] =
                    __floats2half2_rn(h0, h1);
            }
        }
}

// ---------------------------------------------------------------------------
// GEMM2: out = (h @ Wd) * sd  (fp32)
// CTA 128x128, BK=128, 512 threads, 16 warps 2(M) x 8(N), warp tile 64x16,
// 3-stage pipeline (1-chunk lookahead beyond current).
// ---------------------------------------------------------------------------
__global__ void __launch_bounds__(512, 1) gemm2_kernel(float* __restrict__ out) {
    extern __shared__ __align__(128) char sm[];
    const int tid = threadIdx.x, wid = tid >> 5, lid = tid & 31;
    const int m0 = blockIdx.y * 128, n0 = blockIdx.x * 128;
    const int wm0 = (wid & 1) * 64, wn0 = (wid >> 1) * 16;
    const uint32_t sb = smem_u32(sm);

    auto load_chunk = [&](int c, int s) {
        const uint32_t st = sb + s * STG2;
        const int kb = c * BK;
#pragma unroll
        for (int i = 0; i < 4; ++i) {
            int idx = tid + i * 512, row = idx >> 4, seg = idx & 15;
            uint32_t off = (uint32_t)(row * ROWB + seg * 16);
            cp_async16(st + off, g_h + (size_t)(m0 + row) * K2 + kb + seg * 8);
            cp_async16(st + TILEA + off,
                       g_wd + (size_t)(n0 + row) * K2 + kb + seg * 8);
        }
        cp_commit();
    };

    load_chunk(0, 0);
    load_chunk(1, 1);

    float acc[4][2][4];
#pragma unroll
    for (int a = 0; a < 4; ++a)
#pragma unroll
        for (int b = 0; b < 2; ++b)
#pragma unroll
            for (int c = 0; c < 4; ++c) acc[a][b][c] = 0.f;

    const int lr = lid & 15, hc = lid >> 4;
    const uint32_t a_off = (uint32_t)((wm0 + lr) * ROWB + hc * 16);
    const uint32_t b_off = (uint32_t)((wn0 + lr) * ROWB + hc * 16);

#pragma unroll 1
    for (int mc = 0; mc < NC2; ++mc) {
        cp_wait<1>();          // chunk mc resident (mc+1 may be in flight)
        __syncthreads();       // protects stage (mc+2)%3 from late readers
        if (mc + 2 < NC2) load_chunk(mc + 2, (mc + 2) % 3);
        else cp_commit();      // keep group count aligned

        const uint32_t st = sb + (mc % 3) * STG2;
        const uint32_t aB = st + a_off;
        const uint32_t bB = st + TILEA + b_off;

#pragma unroll
        for (int ks = 0; ks < 8; ++ks) {
            const uint32_t ko = ks * 32;
            uint32_t a[4][4], bb[4];
#pragma unroll
            for (int mf = 0; mf < 4; ++mf)
                ldm_x4(a[mf], aB + mf * FSTR + ko);
            ldm_x4(bb, bB + ko);
#pragma unroll
            for (int mf = 0; mf < 4; ++mf)
#pragma unroll
                for (int nf = 0; nf < 2; ++nf)
                    mma16816(acc[mf][nf], a[mf], bb[nf], bb[nf + 2]);
        }
    }

    // ---- epilogue: scale + fp32 store
    const float sd = g_scales[2];
    const int g = lid >> 2, t = lid & 3;
#pragma unroll
    for (int mf = 0; mf < 4; ++mf)
#pragma unroll
        for (int nf = 0; nf < 2; ++nf) {
            const int row0 = m0 + wm0 + mf * 16 + g;
            const int col  = n0 + wn0 + nf * 8 + 2 * t;
            const float* d = acc[mf][nf];
#pragma unroll
            for (int h = 0; h < 2; ++h) {
                float2 v = make_float2(d[2 * h] * sd, d[2 * h + 1] * sd);
                *reinterpret_cast<float2*>(out + (size_t)(row0 + 8 * h) * N2 + col) = v;
            }
        }
}

// ---------------------------------------------------------------------------
// Launch
// ---------------------------------------------------------------------------
extern "C" void kernel_launch(void* const* d_in, const int* in_sizes, int n_in,
                              void* d_out, int out_size) {
    const float* x  = (const float*)d_in[0];
    const float* wg = (const float*)d_in[1];
    const float* wu = (const float*)d_in[2];
    const float* wd = (const float*)d_in[3];
    float* out = (float*)d_out;
    (void)in_sizes; (void)n_in; (void)out_size;

    cudaFuncSetAttribute(gemm1_kernel, cudaFuncAttributeMaxDynamicSharedMemorySize, SMEM1);
    cudaFuncSetAttribute(gemm2_kernel, cudaFuncAttributeMaxDynamicSharedMemorySize, SMEM2);

    // gemm1 stays the 4th launch so ncu's capture window lands on it.
    scales_kernel<<<3, 256>>>(wg, wu, wd);
    build_w_kernel<<<dim3((N1 * K1) / 256, 3), 256>>>(wg, wu, wd);
    convert_x_kernel<<<6144, 256>>>((const float4*)x);
    gemm1_kernel<<<dim3(N1 / 128, M_TOT / 128), 512, SMEM1>>>();
    gemm2_kernel<<<dim3(N2 / 128, M_TOT / 128), 512, SMEM2>>>(out);
}

// round 14
// speedup vs baseline: 1.1939x; 1.1939x over previous
#include <cuda_runtime.h>
#include <cuda_fp16.h>
#include <cstdint>

#define DINL __device__ __forceinline__

// ---------------------------------------------------------------------------
// Problem constants
// ---------------------------------------------------------------------------
namespace {
constexpr int M_TOT = 32768;          // B*T
constexpr int K1 = 768,  N1 = 2048;   // GEMM1: x @ Wg/Wu (fused SwiGLU)
constexpr int K2 = 2048, N2 = 768;    // GEMM2: h @ Wd
constexpr int NC1 = K1 / 64;          // 12 K-chunks
constexpr int NC2 = K2 / 64;          // 32 K-chunks

constexpr int LDK = 72;               // smem halves per row (64 + 8 pad)
constexpr int TILE128 = 128 * LDK * 2;  // 18432 B per 128-row tile
constexpr int TILE64  = 64 * LDK * 2;   //  9216 B per 64-row tile
// GEMM1: CTA 128x64, stage = A(128) + Bg(64) + Bu(64) = 36864
constexpr int STG1 = TILE128 + 2 * TILE64;
// GEMM2: CTA 128x128, stage = A(128) + B(128) = 36864
constexpr int STG2 = 2 * TILE128;
constexpr int NSTG1 = 3;
constexpr int NSTG2 = 3;
constexpr int SMEM1 = NSTG1 * STG1;     // 110592 (x2 CTAs = 221184 / SM)
constexpr int SMEM2 = NSTG2 * STG2;     // 110592
constexpr int FSTRIDE = 16 * LDK * 2;   // 16-row fragment stride in bytes
}

// ---------------------------------------------------------------------------
// Device scratch (static __device__ globals: allocation-free)
// ---------------------------------------------------------------------------
__device__ __half g_x [(size_t)M_TOT * K1];   // x fp16, row-major [32768,768]
__device__ __half g_h [(size_t)M_TOT * N1];   // hidden fp16 [32768,2048]
__device__ __half g_wg[(size_t)N1 * K1];      // gate signs, [n][k]
__device__ __half g_wu[(size_t)N1 * K1];      // up signs,   [n][k]
__device__ __half g_wd[(size_t)N2 * K2];      // down signs, [n][k]
__device__ float  g_scales[3];                // absmean scales: gate, up, down
__device__ double g_part[3][64];              // scale reduction partials

// Octonion Cayley table: e_i * e_j = STAB[i][j] * e_{KTAB[i][j]}
__constant__ signed char KTAB[8][8] = {
    {0,1,2,3,4,5,6,7},
    {1,0,3,2,5,4,7,6},
    {2,3,0,1,6,7,4,5},
    {3,2,1,0,7,6,5,4},
    {4,5,6,7,0,1,2,3},
    {5,4,7,6,1,0,3,2},
    {6,7,4,5,2,3,0,1},
    {7,6,5,4,3,2,1,0},
};
__constant__ signed char STAB[8][8] = {
    { 1, 1, 1, 1, 1, 1, 1, 1},
    { 1,-1, 1,-1, 1,-1,-1, 1},
    { 1,-1,-1, 1, 1, 1,-1,-1},
    { 1, 1,-1,-1, 1,-1, 1,-1},
    { 1,-1,-1,-1,-1, 1, 1, 1},
    { 1, 1,-1, 1,-1,-1,-1, 1},
    { 1, 1, 1,-1,-1, 1,-1,-1},
    { 1,-1, 1, 1,-1,-1, 1,-1},
};

// ---------------------------------------------------------------------------
// PTX helpers (sm_80-portable only)
// ---------------------------------------------------------------------------
DINL uint32_t smem_u32(const void* p) {
    uint32_t a;
    asm("{ .reg .u64 t; cvta.to.shared.u64 t, %1; cvt.u32.u64 %0, t; }"
        : "=r"(a) : "l"(p));
    return a;
}
DINL void cp_async16(uint32_t dst, const void* src) {
    asm volatile("cp.async.cg.shared.global [%0], [%1], 16;"
                 :: "r"(dst), "l"(src) : "memory");
}
DINL void cp_commit() { asm volatile("cp.async.commit_group;" ::: "memory"); }
template <int N> DINL void cp_wait() {
    asm volatile("cp.async.wait_group %0;" :: "n"(N) : "memory");
}
DINL void ldm_x4(uint32_t* r, uint32_t addr) {
    asm volatile("ldmatrix.sync.aligned.m8n8.x4.shared.b16 {%0,%1,%2,%3}, [%4];"
                 : "=r"(r[0]), "=r"(r[1]), "=r"(r[2]), "=r"(r[3]) : "r"(addr));
}
DINL void mma16816(float* d, const uint32_t* a, uint32_t b0, uint32_t b1) {
    asm volatile(
        "mma.sync.aligned.m16n8k16.row.col.f32.f16.f16.f32 "
        "{%0,%1,%2,%3}, {%4,%5,%6,%7}, {%8,%9}, {%0,%1,%2,%3};"
        : "+f"(d[0]), "+f"(d[1]), "+f"(d[2]), "+f"(d[3])
        : "r"(a[0]), "r"(a[1]), "r"(a[2]), "r"(a[3]), "r"(b0), "r"(b1));
}

// ---------------------------------------------------------------------------
// Prep kernels
// ---------------------------------------------------------------------------
// Phase 1: 64 blocks per matrix, each reduces a 3072-element slice (double).
__global__ void scales_part_kernel(const float* wg, const float* wu,
                                   const float* wd) {
    const float* w = (blockIdx.y == 0) ? wg : (blockIdx.y == 1) ? wu : wd;
    __shared__ double red[256];
    const int tid = threadIdx.x;
    const int base = blockIdx.x * 3072;
    double s = 0.0;
#pragma unroll
    for (int i = 0; i < 12; ++i) s += fabsf(w[base + tid + i * 256]);
    red[tid] = s;
    __syncthreads();
    for (int off = 128; off > 0; off >>= 1) {
        if (tid < off) red[tid] += red[tid + off];
        __syncthreads();
    }
    if (tid == 0) g_part[blockIdx.y][blockIdx.x] = red[0];
}

// Phase 2: one block, warp w reduces matrix w's 64 partials (ordered pairs).
__global__ void scales_final_kernel() {
    const int wid = threadIdx.x >> 5, lane = threadIdx.x & 31;
    if (wid >= 3) return;
    double s = g_part[wid][lane] + g_part[wid][lane + 32];
#pragma unroll
    for (int off = 16; off > 0; off >>= 1)
        s += __shfl_down_sync(0xFFFFFFFFu, s, off);
    if (lane == 0)
        g_scales[wid] = (float)(s / 196608.0) + 1e-8f;
}

// Build all three sign matrices. blockIdx.y: 0=gate, 1=up, 2=down.
__global__ void build_w_kernel(const float* wgate, const float* wup,
                               const float* wdown) {
    const int gid = blockIdx.x * 256 + threadIdx.x;
    const int which = blockIdx.y;
    const float scale = g_scales[which];
    float v;
    __half* o;
    if (which < 2) {
        const float* w = which ? wup : wgate;
        const int n = gid / K1, k = gid % K1;
        const int kk = n >> 8, c = n & 255;
        const int i = k / 96, r = k % 96;
        int j = 0;
        while (KTAB[i][j] != kk) ++j;
        v = (float)STAB[i][j] * w[(j * 96 + r) * 256 + c];
        o = which ? g_wu : g_wg;
    } else {
        const int n = gid / K2, k = gid % K2;
        const int kk = n / 96, c = n % 96;
        const int i = k >> 8, r = k & 255;
        int j = 0;
        while (KTAB[i][j] != kk) ++j;
        v = (float)STAB[i][j] * wdown[(j * 256 + r) * 96 + c];
        o = g_wd;
    }
    float q = fminf(fmaxf(rintf(v / scale), -1.f), 1.f);  // exact {-1,0,1}
    o[gid] = __float2half_rn(q);
}

// x fp32 -> fp16
__global__ void convert_x_kernel(const float4* __restrict__ x) {
    const int total4 = (M_TOT * K1) / 4;
    for (int i = blockIdx.x * 256 + threadIdx.x; i < total4; i += 6144 * 256) {
        float4 v = x[i];
        __half2 a = __floats2half2_rn(v.x, v.y);
        __half2 b = __floats2half2_rn(v.z, v.w);
        uint2 pk;
        pk.x = *reinterpret_cast<uint32_t*>(&a);
        pk.y = *reinterpret_cast<uint32_t*>(&b);
        reinterpret_cast<uint2*>(g_x)[i] = pk;
    }
}

// ---------------------------------------------------------------------------
// GEMM1: h = silu(x@Wg * sg) * (x@Wu * su)  -> g_h fp16
// R12 config (best): ping-pong CTA 128x64, 256 threads (8 warps 2(M) x 4(N),
// warp 64x16 x2 gate/up), 3-stage pipeline, 2 CTAs per SM.
// ---------------------------------------------------------------------------
__global__ void __launch_bounds__(256, 2) gemm1_kernel() {
    extern __shared__ __align__(128) char sm[];
    const int tid = threadIdx.x, wid = tid >> 5, lid = tid & 31;
    const int m0 = blockIdx.y * 128, n0 = blockIdx.x * 64;
    const int wm0 = (wid & 1) * 64, wn0 = (wid >> 1) * 16;
    const uint32_t sb = smem_u32(sm);

    auto load_chunk = [&](int c, int s) {
        const uint32_t st = sb + s * STG1;
        const int kb = c * 64;
#pragma unroll
        for (int i = 0; i < 4; ++i) {                 // A: 128 rows x 8 segs
            int idx = tid + i * 256, row = idx >> 3, seg = idx & 7;
            uint32_t off = (uint32_t)(row * LDK + seg * 8) * 2;
            cp_async16(st + off, g_x + (size_t)(m0 + row) * K1 + kb + seg * 8);
        }
#pragma unroll
        for (int i = 0; i < 2; ++i) {                 // Bg, Bu: 64 rows x 8 segs
            int idx = tid + i * 256, row = idx >> 3, seg = idx & 7;
            uint32_t off = (uint32_t)(row * LDK + seg * 8) * 2;
            cp_async16(st + TILE128 + off,
                       g_wg + (size_t)(n0 + row) * K1 + kb + seg * 8);
            cp_async16(st + TILE128 + TILE64 + off,
                       g_wu + (size_t)(n0 + row) * K1 + kb + seg * 8);
        }
        cp_commit();
    };

#pragma unroll
    for (int s = 0; s < NSTG1 - 1; ++s) load_chunk(s, s);

    float accg[4][2][4], accu[4][2][4];
#pragma unroll
    for (int a = 0; a < 4; ++a)
#pragma unroll
        for (int b = 0; b < 2; ++b)
#pragma unroll
            for (int c = 0; c < 4; ++c) { accg[a][b][c] = 0.f; accu[a][b][c] = 0.f; }

    const int lr = lid & 15, hc = lid >> 4;
    const uint32_t a_off = (uint32_t)((wm0 + lr) * LDK + hc * 8) * 2;
    const uint32_t b_off = (uint32_t)((wn0 + lr) * LDK + hc * 8) * 2;

#pragma unroll 1
    for (int mc = 0; mc < NC1; ++mc) {
        cp_wait<NSTG1 - 2>();
        __syncthreads();
        const int lc = mc + NSTG1 - 1;
        if (lc < NC1) load_chunk(lc, lc % NSTG1);
        else cp_commit();

        const uint32_t st  = sb + (mc % NSTG1) * STG1;
        const uint32_t aB  = st + a_off;
        const uint32_t bgB = st + TILE128 + b_off;
        const uint32_t buB = bgB + TILE64;

#pragma unroll
        for (int ks = 0; ks < 4; ++ks) {
            const uint32_t ko = ks * 32;
            uint32_t a[4][4], bg[4], bu[4];
#pragma unroll
            for (int mf = 0; mf < 4; ++mf)
                ldm_x4(a[mf], aB + mf * FSTRIDE + ko);
            ldm_x4(bg, bgB + ko);
            ldm_x4(bu, buB + ko);
#pragma unroll
            for (int mf = 0; mf < 4; ++mf)
#pragma unroll
                for (int nf = 0; nf < 2; ++nf) {
                    mma16816(accg[mf][nf], a[mf], bg[nf], bg[nf + 2]);
                    mma16816(accu[mf][nf], a[mf], bu[nf], bu[nf + 2]);
                }
        }
    }

    // ---- fused SwiGLU epilogue -> g_h (fp16)
    const float sg = g_scales[0], su = g_scales[1];
    const int g = lid >> 2, t = lid & 3;
    __half2* hout = reinterpret_cast<__half2*>(g_h);
#pragma unroll
    for (int mf = 0; mf < 4; ++mf)
#pragma unroll
        for (int nf = 0; nf < 2; ++nf) {
            const int row0 = m0 + wm0 + mf * 16 + g;
            const int col  = n0 + wn0 + nf * 8 + 2 * t;
            const float* dg = accg[mf][nf];
            const float* du = accu[mf][nf];
#pragma unroll
            for (int h = 0; h < 2; ++h) {
                float g0 = dg[2 * h] * sg,     g1 = dg[2 * h + 1] * sg;
                float u0 = du[2 * h] * su,     u1 = du[2 * h + 1] * su;
                float h0 = g0 / (1.f + __expf(-g0)) * u0;
                float h1 = g1 / (1.f + __expf(-g1)) * u1;
                hout[(size_t)(row0 + 8 * h) * (N1 / 2) + (col >> 1)] =
                    __floats2half2_rn(h0, h1);
            }
        }
}

// ---------------------------------------------------------------------------
// GEMM2: out = (h @ Wd) * sd  (fp32)
// R12 config (best): ping-pong CTA 128x128, 256 threads (8 warps 2(M) x 4(N),
// warp 64x32), 3-stage pipeline, 2 CTAs per SM.
// ---------------------------------------------------------------------------
__global__ void __launch_bounds__(256, 2) gemm2_kernel(float* __restrict__ out) {
    extern __shared__ __align__(128) char sm[];
    const int tid = threadIdx.x, wid = tid >> 5, lid = tid & 31;
    const int m0 = blockIdx.y * 128, n0 = blockIdx.x * 128;
    const int wm0 = (wid & 1) * 64, wn0 = (wid >> 1) * 32;
    const uint32_t sb = smem_u32(sm);

    auto load_chunk = [&](int c, int s) {
        const uint32_t st = sb + s * STG2;
        const int kb = c * 64;
#pragma unroll
        for (int i = 0; i < 4; ++i) {                 // A: 128 rows
            int idx = tid + i * 256, row = idx >> 3, seg = idx & 7;
            uint32_t off = (uint32_t)(row * LDK + seg * 8) * 2;
            cp_async16(st + off, g_h + (size_t)(m0 + row) * K2 + kb + seg * 8);
        }
#pragma unroll
        for (int i = 0; i < 4; ++i) {                 // B: 128 rows
            int idx = tid + i * 256, row = idx >> 3, seg = idx & 7;
            uint32_t off = (uint32_t)(row * LDK + seg * 8) * 2;
            cp_async16(st + TILE128 + off,
                       g_wd + (size_t)(n0 + row) * K2 + kb + seg * 8);
        }
        cp_commit();
    };

#pragma unroll
    for (int s = 0; s < NSTG2 - 1; ++s) load_chunk(s, s);

    float acc[4][4][4];
#pragma unroll
    for (int a = 0; a < 4; ++a)
#pragma unroll
        for (int b = 0; b < 4; ++b)
#pragma unroll
            for (int c = 0; c < 4; ++c) acc[a][b][c] = 0.f;

    const int lr = lid & 15, hc = lid >> 4;
    const uint32_t a_off = (uint32_t)((wm0 + lr) * LDK + hc * 8) * 2;
    const uint32_t b_off = (uint32_t)((wn0 + lr) * LDK + hc * 8) * 2;

#pragma unroll 1
    for (int mc = 0; mc < NC2; ++mc) {
        cp_wait<NSTG2 - 2>();
        __syncthreads();
        const int lc = mc + NSTG2 - 1;
        if (lc < NC2) load_chunk(lc, lc % NSTG2);
        else cp_commit();

        const uint32_t st = sb + (mc % NSTG2) * STG2;
        const uint32_t aB = st + a_off;
        const uint32_t bB = st + TILE128 + b_off;

#pragma unroll
        for (int ks = 0; ks < 4; ++ks) {
            const uint32_t ko = ks * 32;
            uint32_t a[4][4], bb[2][4];
#pragma unroll
            for (int mf = 0; mf < 4; ++mf)
                ldm_x4(a[mf], aB + mf * FSTRIDE + ko);
#pragma unroll
            for (int ng = 0; ng < 2; ++ng)
                ldm_x4(bb[ng], bB + ng * FSTRIDE + ko);
#pragma unroll
            for (int mf = 0; mf < 4; ++mf)
#pragma unroll
                for (int nf = 0; nf < 4; ++nf) {
                    const int ng = nf >> 1, sl = nf & 1;
                    mma16816(acc[mf][nf], a[mf], bb[ng][sl], bb[ng][sl + 2]);
                }
        }
    }

    // ---- epilogue: scale + fp32 store
    const float sd = g_scales[2];
    const int g = lid >> 2, t = lid & 3;
#pragma unroll
    for (int mf = 0; mf < 4; ++mf)
#pragma unroll
        for (int nf = 0; nf < 4; ++nf) {
            const int row0 = m0 + wm0 + mf * 16 + g;
            const int col  = n0 + wn0 + nf * 8 + 2 * t;
            const float* d = acc[mf][nf];
#pragma unroll
            for (int h = 0; h < 2; ++h) {
                float2 v = make_float2(d[2 * h] * sd, d[2 * h + 1] * sd);
                *reinterpret_cast<float2*>(out + (size_t)(row0 + 8 * h) * N2 + col) = v;
            }
        }
}

// ---------------------------------------------------------------------------
// Launch
// ---------------------------------------------------------------------------
extern "C" void kernel_launch(void* const* d_in, const int* in_sizes, int n_in,
                              void* d_out, int out_size) {
    const float* x  = (const float*)d_in[0];
    const float* wg = (const float*)d_in[1];
    const float* wu = (const float*)d_in[2];
    const float* wd = (const float*)d_in[3];
    float* out = (float*)d_out;
    (void)in_sizes; (void)n_in; (void)out_size;

    cudaFuncSetAttribute(gemm1_kernel, cudaFuncAttributeMaxDynamicSharedMemorySize, SMEM1);
    cudaFuncSetAttribute(gemm2_kernel, cudaFuncAttributeMaxDynamicSharedMemorySize, SMEM2);

    scales_part_kernel<<<dim3(64, 3), 256>>>(wg, wu, wd);
    scales_final_kernel<<<1, 96>>>();
    build_w_kernel<<<dim3((N1 * K1) / 256, 3), 256>>>(wg, wu, wd);
    convert_x_kernel<<<6144, 256>>>((const float4*)x);
    gemm1_kernel<<<dim3(N1 / 64, M_TOT / 128), 256, SMEM1>>>();
    gemm2_kernel<<<dim3(N2 / 128, M_TOT / 128), 256, SMEM2>>>(out);
}